// round 14
// baseline (speedup 1.0000x reference)
#include <cuda_runtime.h>
#include <cuda_bf16.h>
#include <mma.h>
#include <cstdint>

using namespace nvcuda;

// Problem constants
#define BATCH   2
#define LSEQ    4096
#define DIMSZ   512
#define NHEADS  8
#define HD      64
#define KSZ     33
#define MROWS   (BATCH * LSEQ)        // 8192
#define QKVDIM  (3 * DIMSZ)           // 1536
#define KIN     512
#define K2      1024                  // [hi|lo] compact layout
#define BQ      128

// GEMM tiling: CTA 128x256, 16 warps (4x4), warp tile 32x64
#define MT      128
#define NT      256
#define KC      64
#define NIT     (KIN / KC)            // 8
#define SRD     72
#define AT_B    (128 * SRD * 2)       // 18432
#define BT_B    (256 * SRD * 2)       // 36864
#define STAGE_BYTES (2 * AT_B + 2 * BT_B)   // 110592
#define SM_TOTAL (2 * STAGE_BYTES)          // 221184

// Attention
#define KVP     66
#define ATT_SMEM (2 * 160 * KVP * 4)  // 84480

// Scratch (device globals; allocation is forbidden)
__device__ float          g_qkv[(size_t)MROWS * QKVDIM];
__device__ __nv_bfloat16  g_a2 [(size_t)MROWS * K2];     // [hi|lo]
__device__ __nv_bfloat16  g_wq2[(size_t)QKVDIM * K2];
__device__ __nv_bfloat16  g_wp2[(size_t)DIMSZ * K2];

typedef unsigned long long ull;

__device__ __forceinline__ uint32_t cvta_smem(const void* p) {
    uint32_t a;
    asm("{ .reg .u64 t; cvta.to.shared.u64 t, %1; cvt.u32.u64 %0, t; }"
        : "=r"(a) : "l"(p));
    return a;
}

// Packed fp32x2 ops (Blackwell FFMA2 path)
__device__ __forceinline__ ull pk2(float x, float y) {
    ull r; asm("mov.b64 %0, {%1, %2};" : "=l"(r) : "f"(x), "f"(y)); return r;
}
__device__ __forceinline__ void upk2(ull v, float& x, float& y) {
    asm("mov.b64 {%0, %1}, %2;" : "=f"(x), "=f"(y) : "l"(v));
}
__device__ __forceinline__ ull ffma2(ull a, ull b, ull c) {
    ull d; asm("fma.rn.f32x2 %0, %1, %2, %3;" : "=l"(d) : "l"(a), "l"(b), "l"(c));
    return d;
}
__device__ __forceinline__ ull fadd2(ull a, ull b) {
    ull d; asm("add.rn.f32x2 %0, %1, %2;" : "=l"(d) : "l"(a), "l"(b));
    return d;
}

// ---------------------------------------------------------------------------
// Merged fp32 -> compact split-bf16 for all three operands in one launch.
// ---------------------------------------------------------------------------
__global__ void __launch_bounds__(256) split_bf16_all(
    const float4* __restrict__ inx,  __nv_bfloat16* __restrict__ outx,
    const float4* __restrict__ inq,  __nv_bfloat16* __restrict__ outq,
    const float4* __restrict__ inp,  __nv_bfloat16* __restrict__ outp)
{
    const float4* in;
    __nv_bfloat16* out;
    int base;
    int bid = blockIdx.x;
    if (bid < 4096)      { in = inx; out = outx; base = bid; }
    else if (bid < 4864) { in = inq; out = outq; base = bid - 4096; }
    else                 { in = inp; out = outp; base = bid - 4864; }

    int i = base * 256 + threadIdx.x;
    int row = i >> 7;
    int k   = (i & 127) * 4;
    float4 x = in[i];
    __nv_bfloat16 h0 = __float2bfloat16(x.x), h1 = __float2bfloat16(x.y);
    __nv_bfloat16 h2 = __float2bfloat16(x.z), h3 = __float2bfloat16(x.w);
    __nv_bfloat16 l0 = __float2bfloat16(x.x - __bfloat162float(h0));
    __nv_bfloat16 l1 = __float2bfloat16(x.y - __bfloat162float(h1));
    __nv_bfloat16 l2 = __float2bfloat16(x.z - __bfloat162float(h2));
    __nv_bfloat16 l3 = __float2bfloat16(x.w - __bfloat162float(h3));
    __nv_bfloat16* bp = out + (size_t)row * K2;
    __nv_bfloat162* ph = (__nv_bfloat162*)(bp + k);
    __nv_bfloat162* pl = (__nv_bfloat162*)(bp + KIN + k);
    ph[0] = {h0, h1}; ph[1] = {h2, h3};
    pl[0] = {l0, l1}; pl[1] = {l2, l3};
}

// ---------------------------------------------------------------------------
// wmma GEMM with 3-term split accumulation (frozen — at legacy HMMA plateau)
// ---------------------------------------------------------------------------
__global__ void __launch_bounds__(512, 1) gemm_wmma(
    const __nv_bfloat16* __restrict__ A, const __nv_bfloat16* __restrict__ B,
    const float* __restrict__ bias, float* __restrict__ C, int N)
{
    extern __shared__ char sh[];
    const uint32_t sbase = cvta_smem(sh);

    const int tid  = threadIdx.x;
    const int wid  = tid >> 5;
    const int wm   = wid >> 2;
    const int wn   = wid & 3;
    const int m0 = blockIdx.y * MT;
    const int n0 = blockIdx.x * NT;

    const __nv_bfloat16* Ag = A + (size_t)m0 * K2;
    const __nv_bfloat16* Bg = B + (size_t)n0 * K2;

    float* bias_t = (float*)sh;
    for (int idx = tid; idx < 16 * NT; idx += 512)
        bias_t[idx] = bias[n0 + (idx & (NT - 1))];
    __syncthreads();

    wmma::fragment<wmma::accumulator, 16, 16, 16, float> acc[2][4];
#pragma unroll
    for (int i = 0; i < 2; i++)
#pragma unroll
        for (int j = 0; j < 4; j++)
            wmma::load_matrix_sync(acc[i][j],
                                   bias_t + wn * 64 + j * 16, NT,
                                   wmma::mem_row_major);
    __syncthreads();

    auto load_stage = [&](int stage, int it) {
        const int kc = it * KC;
        const uint32_t s0 = sbase + stage * STAGE_BYTES;
#pragma unroll
        for (int t = 0; t < 4; t++) {
            int idx = tid + t * 512;
            int half = idx >> 10;
            int row  = (idx >> 3) & 127;
            int c16  = idx & 7;
            uint32_t dst = s0 + half * AT_B + row * (SRD * 2) + c16 * 16;
            const void* src = Ag + (size_t)row * K2 + half * KIN + kc + c16 * 8;
            asm volatile("cp.async.cg.shared.global [%0], [%1], 16;"
                         :: "r"(dst), "l"(src));
        }
#pragma unroll
        for (int t = 0; t < 8; t++) {
            int idx = tid + t * 512;
            int half = idx >> 11;
            int row  = (idx >> 3) & 255;
            int c16  = idx & 7;
            uint32_t dst = s0 + 2 * AT_B + half * BT_B + row * (SRD * 2) + c16 * 16;
            const void* src = Bg + (size_t)row * K2 + half * KIN + kc + c16 * 8;
            asm volatile("cp.async.cg.shared.global [%0], [%1], 16;"
                         :: "r"(dst), "l"(src));
        }
    };

    load_stage(0, 0);
    asm volatile("cp.async.commit_group;" ::: "memory");
    load_stage(1, 1);
    asm volatile("cp.async.commit_group;" ::: "memory");

    for (int it = 0; it < NIT; it++) {
        if (it + 1 < NIT)
            asm volatile("cp.async.wait_group 1;" ::: "memory");
        else
            asm volatile("cp.async.wait_group 0;" ::: "memory");
        __syncthreads();

        const char* stg = sh + (it & 1) * STAGE_BYTES;
        const __nv_bfloat16* Ahi = (const __nv_bfloat16*)stg;
        const __nv_bfloat16* Alo = (const __nv_bfloat16*)(stg + AT_B);
        const __nv_bfloat16* Bhi = (const __nv_bfloat16*)(stg + 2 * AT_B);
        const __nv_bfloat16* Blo = (const __nv_bfloat16*)(stg + 2 * AT_B + BT_B);

#pragma unroll
        for (int ks = 0; ks < 4; ks++) {
            wmma::fragment<wmma::matrix_a, 16, 16, 16, __nv_bfloat16,
                           wmma::row_major> af[2];
            wmma::fragment<wmma::matrix_b, 16, 16, 16, __nv_bfloat16,
                           wmma::col_major> bfh[4], bfl[4];
#pragma unroll
            for (int i = 0; i < 2; i++)
                wmma::load_matrix_sync(af[i],
                    Ahi + (size_t)(wm * 32 + i * 16) * SRD + ks * 16, SRD);
#pragma unroll
            for (int j = 0; j < 4; j++)
                wmma::load_matrix_sync(bfh[j],
                    Bhi + (size_t)(wn * 64 + j * 16) * SRD + ks * 16, SRD);
#pragma unroll
            for (int i = 0; i < 2; i++)
#pragma unroll
                for (int j = 0; j < 4; j++)
                    wmma::mma_sync(acc[i][j], af[i], bfh[j], acc[i][j]);
#pragma unroll
            for (int j = 0; j < 4; j++)
                wmma::load_matrix_sync(bfl[j],
                    Blo + (size_t)(wn * 64 + j * 16) * SRD + ks * 16, SRD);
#pragma unroll
            for (int i = 0; i < 2; i++)
#pragma unroll
                for (int j = 0; j < 4; j++)
                    wmma::mma_sync(acc[i][j], af[i], bfl[j], acc[i][j]);
#pragma unroll
            for (int i = 0; i < 2; i++)
                wmma::load_matrix_sync(af[i],
                    Alo + (size_t)(wm * 32 + i * 16) * SRD + ks * 16, SRD);
#pragma unroll
            for (int i = 0; i < 2; i++)
#pragma unroll
                for (int j = 0; j < 4; j++)
                    wmma::mma_sync(acc[i][j], af[i], bfh[j], acc[i][j]);
        }
        __syncthreads();

        const int nx = it + 2;
        if (nx < NIT) {
            load_stage(nx & 1, nx);
            asm volatile("cp.async.commit_group;" ::: "memory");
        }
    }

#pragma unroll
    for (int i = 0; i < 2; i++)
#pragma unroll
        for (int j = 0; j < 4; j++)
            wmma::store_matrix_sync(
                C + (size_t)(m0 + wm * 32 + i * 16) * N + n0 + wn * 64 + j * 16,
                acc[i][j], N, wmma::mem_row_major);
}

// ---------------------------------------------------------------------------
// Neighborhood attention. NEW: batched-register staging (5 predicated LDG.128
// per operand, then stores) — removes the serial LDG->STS latency chain.
// Math identical to R12: FFMA2 dots, dedup exp, fused split epilogue.
// ---------------------------------------------------------------------------
__global__ void __launch_bounds__(512) na1d_kernel(
    const float* __restrict__ qkv, __nv_bfloat16* __restrict__ out2)
{
    extern __shared__ float shf[];
    float* Ks = shf;                  // [160][KVP]
    float* Vs = shf + 160 * KVP;

    const int tid = threadIdx.x;
    const int b  = blockIdx.z;
    const int h  = blockIdx.y;
    const int q0 = blockIdx.x * BQ;

    const int smin = min(max(q0 - (KSZ / 2), 0), LSEQ - KSZ);
    const int smax = min(max(q0 + BQ - 1 - (KSZ / 2), 0), LSEQ - KSZ);
    const int nk   = smax - smin + KSZ;   // <= 160
    const int lim  = nk * 16;             // 16B units per operand (<= 2560)

    // Batched staging: load phase (latency overlapped across 5+5 LDG.128),
    // then store phase. Row = idx>>4, 16B-chunk = idx&15.
    const float* kb = qkv + ((size_t)(b * LSEQ + smin)) * QKVDIM + DIMSZ + h * HD;
    {
        uint4 kreg[5], vreg[5];
#pragma unroll
        for (int i = 0; i < 5; i++) {
            int idx = tid + i * 512;
            if (idx < lim) {
                int row = idx >> 4, c = (idx & 15) * 4;
                kreg[i] = *(const uint4*)(kb + (size_t)row * QKVDIM + c);
                vreg[i] = *(const uint4*)(kb + (size_t)row * QKVDIM + DIMSZ + c);
            }
        }
#pragma unroll
        for (int i = 0; i < 5; i++) {
            int idx = tid + i * 512;
            if (idx < lim) {
                int row = idx >> 4, c = (idx & 15) * 4;
                ull* kd = (ull*)(Ks + row * KVP + c);
                kd[0] = ((ull)kreg[i].y << 32) | kreg[i].x;
                kd[1] = ((ull)kreg[i].w << 32) | kreg[i].z;
                ull* vd = (ull*)(Vs + row * KVP + c);
                vd[0] = ((ull)vreg[i].y << 32) | vreg[i].x;
                vd[1] = ((ull)vreg[i].w << 32) | vreg[i].z;
            }
        }
    }
    __syncthreads();

    const int lane    = tid & 31;
    const int quarter = tid & 3;
    const int l  = q0 + (tid >> 2);
    const int dp = quarter * 16;
    const int st  = min(max(l - (KSZ / 2), 0), LSEQ - KSZ);
    const int ks0 = st - smin;

    // q slice, scaled, packed into 8 f32x2 registers
    const float* qp = qkv + ((size_t)(b * LSEQ + l)) * QKVDIM + h * HD + dp;
    ull q2[8];
#pragma unroll
    for (int s = 0; s < 8; s += 2) {
        float4 v = *(const float4*)(qp + s * 2);
        q2[s]     = pk2(v.x * 0.125f, v.y * 0.125f);
        q2[s + 1] = pk2(v.z * 0.125f, v.w * 0.125f);
    }

    // Scores via packed FFMA2
    float sc[KSZ];
    float mx = -1e30f;
#pragma unroll
    for (int j = 0; j < KSZ; j++) {
        const ull* kr2 = (const ull*)(Ks + (ks0 + j) * KVP + dp);
        ull a0 = 0ULL, a1 = 0ULL;
#pragma unroll
        for (int s = 0; s < 8; s += 2) {
            a0 = ffma2(q2[s],     kr2[s],     a0);
            a1 = ffma2(q2[s + 1], kr2[s + 1], a1);
        }
        ull a = fadd2(a0, a1);
        float x, y;
        upk2(a, x, y);
        float p = x + y;
        p += __shfl_xor_sync(0xFFFFFFFF, p, 1);
        p += __shfl_xor_sync(0xFFFFFFFF, p, 2);
        sc[j] = p;
        mx = fmaxf(mx, p);
    }

    // Deduplicated exp: this thread evaluates only j == quarter (mod 4)
    float pj[9];
    float sum_part = 0.0f;
#pragma unroll
    for (int jj = 0; jj < 9; jj++) {
        int j = jj * 4 + quarter;
        if (j < KSZ) {
            float e = __expf(sc[j] - mx);
            pj[jj] = e;
            sum_part += e;
        } else {
            pj[jj] = 0.0f;
        }
    }
    float sum = sum_part;
    sum += __shfl_xor_sync(0xFFFFFFFF, sum, 1);
    sum += __shfl_xor_sync(0xFFFFFFFF, sum, 2);
    const float inv = 1.0f / sum;

    // Output accumulation; p_j broadcast from owning thread in the 4-group
    ull o2[8];
#pragma unroll
    for (int s = 0; s < 8; s++) o2[s] = 0ULL;
#pragma unroll
    for (int j = 0; j < KSZ; j++) {
        float p = __shfl_sync(0xFFFFFFFF, pj[j >> 2], (lane & ~3) | (j & 3));
        const ull p2 = pk2(p, p);
        const ull* vr2 = (const ull*)(Vs + (ks0 + j) * KVP + dp);
#pragma unroll
        for (int s = 0; s < 8; s++)
            o2[s] = ffma2(p2, vr2[s], o2[s]);
    }

    // Fused split epilogue: write [hi|lo] bf16 directly
    __nv_bfloat16* orow = out2 + (size_t)(b * LSEQ + l) * K2 + h * HD + dp;
    __nv_bfloat162* ph = (__nv_bfloat162*)orow;
    __nv_bfloat162* pl = (__nv_bfloat162*)(orow + KIN);
#pragma unroll
    for (int s = 0; s < 8; s++) {
        float x, y;
        upk2(o2[s], x, y);
        x *= inv; y *= inv;
        __nv_bfloat16 hx = __float2bfloat16(x);
        __nv_bfloat16 hy = __float2bfloat16(y);
        __nv_bfloat16 lx = __float2bfloat16(x - __bfloat162float(hx));
        __nv_bfloat16 ly = __float2bfloat16(y - __bfloat162float(hy));
        ph[s] = {hx, hy};
        pl[s] = {lx, ly};
    }
}

// ---------------------------------------------------------------------------
// Launch
// ---------------------------------------------------------------------------
extern "C" void kernel_launch(void* const* d_in, const int* in_sizes, int n_in,
                              void* d_out, int out_size)
{
    const float* x      = (const float*)d_in[0];
    const float* w_qkv  = (const float*)d_in[1];
    const float* b_qkv  = (const float*)d_in[2];
    const float* w_proj = (const float*)d_in[3];
    const float* b_proj = (const float*)d_in[4];
    float*       out    = (float*)d_out;

    float* qkv;
    __nv_bfloat16 *a2, *wq2, *wp2;
    cudaGetSymbolAddress((void**)&qkv, g_qkv);
    cudaGetSymbolAddress((void**)&a2,  g_a2);
    cudaGetSymbolAddress((void**)&wq2, g_wq2);
    cudaGetSymbolAddress((void**)&wp2, g_wp2);

    cudaFuncSetAttribute(na1d_kernel,
                         cudaFuncAttributeMaxDynamicSharedMemorySize, ATT_SMEM);
    cudaFuncSetAttribute(gemm_wmma,
                         cudaFuncAttributeMaxDynamicSharedMemorySize, SM_TOTAL);

    // All three [hi|lo] splits in one launch
    split_bf16_all<<<5120, 256>>>((const float4*)x, a2,
                                  (const float4*)w_qkv, wq2,
                                  (const float4*)w_proj, wp2);

    // 1) QKV projection
    dim3 g1(QKVDIM / NT, MROWS / MT);
    gemm_wmma<<<g1, 512, SM_TOTAL>>>(a2, wq2, b_qkv, qkv, QKVDIM);

    // 2) Neighborhood attention (writes split [hi|lo] operand directly)
    dim3 g2(LSEQ / BQ, NHEADS, BATCH);
    na1d_kernel<<<g2, 512, ATT_SMEM>>>(qkv, a2);

    // 3) Output projection
    dim3 g3(DIMSZ / NT, MROWS / MT);
    gemm_wmma<<<g3, 512, SM_TOTAL>>>(a2, wp2, b_proj, out, DIMSZ);
}

// round 15
// speedup vs baseline: 1.1274x; 1.1274x over previous
#include <cuda_runtime.h>
#include <cuda_bf16.h>
#include <mma.h>
#include <cstdint>

using namespace nvcuda;

// Problem constants
#define BATCH   2
#define LSEQ    4096
#define DIMSZ   512
#define NHEADS  8
#define HD      64
#define KSZ     33
#define MROWS   (BATCH * LSEQ)        // 8192
#define QKVDIM  (3 * DIMSZ)           // 1536
#define KIN     512
#define K2      1024                  // [hi|lo] compact layout
#define BQ      128

// GEMM tiling: CTA 128x256, 16 warps (4x4), warp tile 32x64
#define MT      128
#define NT      256
#define KC      64
#define NIT     (KIN / KC)            // 8
#define SRD     72
#define AT_B    (128 * SRD * 2)       // 18432
#define BT_B    (256 * SRD * 2)       // 36864
#define STAGE_BYTES (2 * AT_B + 2 * BT_B)   // 110592
#define SM_TOTAL (2 * STAGE_BYTES)          // 221184

// Attention
#define KVP     66
#define ATT_SMEM (2 * 160 * KVP * 4)  // 84480

// Scratch (device globals; allocation is forbidden)
__device__ float          g_qkv[(size_t)MROWS * QKVDIM];
__device__ __nv_bfloat16  g_a2 [(size_t)MROWS * K2];     // [hi|lo]
__device__ __nv_bfloat16  g_wq2[(size_t)QKVDIM * K2];
__device__ __nv_bfloat16  g_wp2[(size_t)DIMSZ * K2];

typedef unsigned long long ull;

__device__ __forceinline__ uint32_t cvta_smem(const void* p) {
    uint32_t a;
    asm("{ .reg .u64 t; cvta.to.shared.u64 t, %1; cvt.u32.u64 %0, t; }"
        : "=r"(a) : "l"(p));
    return a;
}

// Packed fp32x2 ops (Blackwell FFMA2 path)
__device__ __forceinline__ ull pk2(float x, float y) {
    ull r; asm("mov.b64 %0, {%1, %2};" : "=l"(r) : "f"(x), "f"(y)); return r;
}
__device__ __forceinline__ void upk2(ull v, float& x, float& y) {
    asm("mov.b64 {%0, %1}, %2;" : "=f"(x), "=f"(y) : "l"(v));
}
__device__ __forceinline__ ull ffma2(ull a, ull b, ull c) {
    ull d; asm("fma.rn.f32x2 %0, %1, %2, %3;" : "=l"(d) : "l"(a), "l"(b), "l"(c));
    return d;
}
__device__ __forceinline__ ull fadd2(ull a, ull b) {
    ull d; asm("add.rn.f32x2 %0, %1, %2;" : "=l"(d) : "l"(a), "l"(b));
    return d;
}

// ---------------------------------------------------------------------------
// Merged fp32 -> compact split-bf16 for all three operands in one launch.
// ---------------------------------------------------------------------------
__global__ void __launch_bounds__(256) split_bf16_all(
    const float4* __restrict__ inx,  __nv_bfloat16* __restrict__ outx,
    const float4* __restrict__ inq,  __nv_bfloat16* __restrict__ outq,
    const float4* __restrict__ inp,  __nv_bfloat16* __restrict__ outp)
{
    const float4* in;
    __nv_bfloat16* out;
    int base;
    int bid = blockIdx.x;
    if (bid < 4096)      { in = inx; out = outx; base = bid; }
    else if (bid < 4864) { in = inq; out = outq; base = bid - 4096; }
    else                 { in = inp; out = outp; base = bid - 4864; }

    int i = base * 256 + threadIdx.x;
    int row = i >> 7;
    int k   = (i & 127) * 4;
    float4 x = in[i];
    __nv_bfloat16 h0 = __float2bfloat16(x.x), h1 = __float2bfloat16(x.y);
    __nv_bfloat16 h2 = __float2bfloat16(x.z), h3 = __float2bfloat16(x.w);
    __nv_bfloat16 l0 = __float2bfloat16(x.x - __bfloat162float(h0));
    __nv_bfloat16 l1 = __float2bfloat16(x.y - __bfloat162float(h1));
    __nv_bfloat16 l2 = __float2bfloat16(x.z - __bfloat162float(h2));
    __nv_bfloat16 l3 = __float2bfloat16(x.w - __bfloat162float(h3));
    __nv_bfloat16* bp = out + (size_t)row * K2;
    __nv_bfloat162* ph = (__nv_bfloat162*)(bp + k);
    __nv_bfloat162* pl = (__nv_bfloat162*)(bp + KIN + k);
    ph[0] = {h0, h1}; ph[1] = {h2, h3};
    pl[0] = {l0, l1}; pl[1] = {l2, l3};
}

// ---------------------------------------------------------------------------
// wmma GEMM with 3-term split accumulation (frozen — at legacy HMMA plateau)
// ---------------------------------------------------------------------------
__global__ void __launch_bounds__(512, 1) gemm_wmma(
    const __nv_bfloat16* __restrict__ A, const __nv_bfloat16* __restrict__ B,
    const float* __restrict__ bias, float* __restrict__ C, int N)
{
    extern __shared__ char sh[];
    const uint32_t sbase = cvta_smem(sh);

    const int tid  = threadIdx.x;
    const int wid  = tid >> 5;
    const int wm   = wid >> 2;
    const int wn   = wid & 3;
    const int m0 = blockIdx.y * MT;
    const int n0 = blockIdx.x * NT;

    const __nv_bfloat16* Ag = A + (size_t)m0 * K2;
    const __nv_bfloat16* Bg = B + (size_t)n0 * K2;

    float* bias_t = (float*)sh;
    for (int idx = tid; idx < 16 * NT; idx += 512)
        bias_t[idx] = bias[n0 + (idx & (NT - 1))];
    __syncthreads();

    wmma::fragment<wmma::accumulator, 16, 16, 16, float> acc[2][4];
#pragma unroll
    for (int i = 0; i < 2; i++)
#pragma unroll
        for (int j = 0; j < 4; j++)
            wmma::load_matrix_sync(acc[i][j],
                                   bias_t + wn * 64 + j * 16, NT,
                                   wmma::mem_row_major);
    __syncthreads();

    auto load_stage = [&](int stage, int it) {
        const int kc = it * KC;
        const uint32_t s0 = sbase + stage * STAGE_BYTES;
#pragma unroll
        for (int t = 0; t < 4; t++) {
            int idx = tid + t * 512;
            int half = idx >> 10;
            int row  = (idx >> 3) & 127;
            int c16  = idx & 7;
            uint32_t dst = s0 + half * AT_B + row * (SRD * 2) + c16 * 16;
            const void* src = Ag + (size_t)row * K2 + half * KIN + kc + c16 * 8;
            asm volatile("cp.async.cg.shared.global [%0], [%1], 16;"
                         :: "r"(dst), "l"(src));
        }
#pragma unroll
        for (int t = 0; t < 8; t++) {
            int idx = tid + t * 512;
            int half = idx >> 11;
            int row  = (idx >> 3) & 255;
            int c16  = idx & 7;
            uint32_t dst = s0 + 2 * AT_B + half * BT_B + row * (SRD * 2) + c16 * 16;
            const void* src = Bg + (size_t)row * K2 + half * KIN + kc + c16 * 8;
            asm volatile("cp.async.cg.shared.global [%0], [%1], 16;"
                         :: "r"(dst), "l"(src));
        }
    };

    load_stage(0, 0);
    asm volatile("cp.async.commit_group;" ::: "memory");
    load_stage(1, 1);
    asm volatile("cp.async.commit_group;" ::: "memory");

    for (int it = 0; it < NIT; it++) {
        if (it + 1 < NIT)
            asm volatile("cp.async.wait_group 1;" ::: "memory");
        else
            asm volatile("cp.async.wait_group 0;" ::: "memory");
        __syncthreads();

        const char* stg = sh + (it & 1) * STAGE_BYTES;
        const __nv_bfloat16* Ahi = (const __nv_bfloat16*)stg;
        const __nv_bfloat16* Alo = (const __nv_bfloat16*)(stg + AT_B);
        const __nv_bfloat16* Bhi = (const __nv_bfloat16*)(stg + 2 * AT_B);
        const __nv_bfloat16* Blo = (const __nv_bfloat16*)(stg + 2 * AT_B + BT_B);

#pragma unroll
        for (int ks = 0; ks < 4; ks++) {
            wmma::fragment<wmma::matrix_a, 16, 16, 16, __nv_bfloat16,
                           wmma::row_major> af[2];
            wmma::fragment<wmma::matrix_b, 16, 16, 16, __nv_bfloat16,
                           wmma::col_major> bfh[4], bfl[4];
#pragma unroll
            for (int i = 0; i < 2; i++)
                wmma::load_matrix_sync(af[i],
                    Ahi + (size_t)(wm * 32 + i * 16) * SRD + ks * 16, SRD);
#pragma unroll
            for (int j = 0; j < 4; j++)
                wmma::load_matrix_sync(bfh[j],
                    Bhi + (size_t)(wn * 64 + j * 16) * SRD + ks * 16, SRD);
#pragma unroll
            for (int i = 0; i < 2; i++)
#pragma unroll
                for (int j = 0; j < 4; j++)
                    wmma::mma_sync(acc[i][j], af[i], bfh[j], acc[i][j]);
#pragma unroll
            for (int j = 0; j < 4; j++)
                wmma::load_matrix_sync(bfl[j],
                    Blo + (size_t)(wn * 64 + j * 16) * SRD + ks * 16, SRD);
#pragma unroll
            for (int i = 0; i < 2; i++)
#pragma unroll
                for (int j = 0; j < 4; j++)
                    wmma::mma_sync(acc[i][j], af[i], bfl[j], acc[i][j]);
#pragma unroll
            for (int i = 0; i < 2; i++)
                wmma::load_matrix_sync(af[i],
                    Alo + (size_t)(wm * 32 + i * 16) * SRD + ks * 16, SRD);
#pragma unroll
            for (int i = 0; i < 2; i++)
#pragma unroll
                for (int j = 0; j < 4; j++)
                    wmma::mma_sync(acc[i][j], af[i], bfh[j], acc[i][j]);
        }
        __syncthreads();

        const int nx = it + 2;
        if (nx < NIT) {
            load_stage(nx & 1, nx);
            asm volatile("cp.async.commit_group;" ::: "memory");
        }
    }

#pragma unroll
    for (int i = 0; i < 2; i++)
#pragma unroll
        for (int j = 0; j < 4; j++)
            wmma::store_matrix_sync(
                C + (size_t)(m0 + wm * 32 + i * 16) * N + n0 + wn * 64 + j * 16,
                acc[i][j], N, wmma::mem_row_major);
}

// ---------------------------------------------------------------------------
// Neighborhood attention, 2 QUERIES PER THREAD (K/V row loaded once, used
// twice -> smem traffic halved; 256 threads -> 2 CTAs/SM).
// 4 threads per query-pair; window union <= 34 rows, d = st(l+1)-st(l) in {0,1}.
// FFMA2 dots, dedup exp (inactive scores -> -1e30 -> exp 0), fused split out.
// ---------------------------------------------------------------------------
__global__ void __launch_bounds__(256) na1d_kernel(
    const float* __restrict__ qkv, __nv_bfloat16* __restrict__ out2)
{
    extern __shared__ float shf[];
    float* Ks = shf;                  // [160][KVP]
    float* Vs = shf + 160 * KVP;

    const int tid = threadIdx.x;
    const int b  = blockIdx.z;
    const int h  = blockIdx.y;
    const int q0 = blockIdx.x * BQ;

    const int smin = min(max(q0 - (KSZ / 2), 0), LSEQ - KSZ);
    const int smax = min(max(q0 + BQ - 1 - (KSZ / 2), 0), LSEQ - KSZ);
    const int nk   = smax - smin + KSZ;   // <= 160
    const int lim  = nk * 16;             // 16B units per operand (<= 2560)

    // Batched staging with 256 threads: 2 rounds of 5 predicated LDG.128
    const float* kb = qkv + ((size_t)(b * LSEQ + smin)) * QKVDIM + DIMSZ + h * HD;
#pragma unroll
    for (int r = 0; r < 2; r++) {
        uint4 kreg[5], vreg[5];
#pragma unroll
        for (int i = 0; i < 5; i++) {
            int idx = tid + (r * 5 + i) * 256;
            if (idx < lim) {
                int row = idx >> 4, c = (idx & 15) * 4;
                kreg[i] = *(const uint4*)(kb + (size_t)row * QKVDIM + c);
                vreg[i] = *(const uint4*)(kb + (size_t)row * QKVDIM + DIMSZ + c);
            }
        }
#pragma unroll
        for (int i = 0; i < 5; i++) {
            int idx = tid + (r * 5 + i) * 256;
            if (idx < lim) {
                int row = idx >> 4, c = (idx & 15) * 4;
                ull* kd = (ull*)(Ks + row * KVP + c);
                kd[0] = ((ull)kreg[i].y << 32) | kreg[i].x;
                kd[1] = ((ull)kreg[i].w << 32) | kreg[i].z;
                ull* vd = (ull*)(Vs + row * KVP + c);
                vd[0] = ((ull)vreg[i].y << 32) | vreg[i].x;
                vd[1] = ((ull)vreg[i].w << 32) | vreg[i].z;
            }
        }
    }
    __syncthreads();

    const int lane    = tid & 31;
    const int quarter = tid & 3;
    const int l0 = q0 + 2 * (tid >> 2);
    const int l1 = l0 + 1;
    const int dp = quarter * 16;
    const int st0 = min(max(l0 - (KSZ / 2), 0), LSEQ - KSZ);
    const int st1 = min(max(l1 - (KSZ / 2), 0), LSEQ - KSZ);
    const int base = st0 - smin;
    const int d    = st1 - st0;           // 0 or 1

    // q slices for both queries, scaled, packed
    const float* qp0 = qkv + ((size_t)(b * LSEQ + l0)) * QKVDIM + h * HD + dp;
    const float* qp1 = qkv + ((size_t)(b * LSEQ + l1)) * QKVDIM + h * HD + dp;
    ull q0r[8], q1r[8];
#pragma unroll
    for (int s = 0; s < 8; s += 2) {
        float4 v0 = *(const float4*)(qp0 + s * 2);
        q0r[s]     = pk2(v0.x * 0.125f, v0.y * 0.125f);
        q0r[s + 1] = pk2(v0.z * 0.125f, v0.w * 0.125f);
        float4 v1 = *(const float4*)(qp1 + s * 2);
        q1r[s]     = pk2(v1.x * 0.125f, v1.y * 0.125f);
        q1r[s + 1] = pk2(v1.z * 0.125f, v1.w * 0.125f);
    }

    // Score loop over union rows (34 iters); keep only owned scores
    float s0own[9], s1own[9];
    float mx0 = -1e30f, mx1 = -1e30f;
#pragma unroll
    for (int jj = 0; jj < 34; jj++) {
        int row = base + ((jj == 33 && d == 0) ? 32 : jj);
        const ull* kr2 = (const ull*)(Ks + row * KVP + dp);
        ull a0 = 0ULL, a1 = 0ULL;
#pragma unroll
        for (int s = 0; s < 8; s++) {
            ull kv = kr2[s];
            a0 = ffma2(q0r[s], kv, a0);
            a1 = ffma2(q1r[s], kv, a1);
        }
        float x0, y0, x1, y1;
        upk2(a0, x0, y0);
        upk2(a1, x1, y1);
        float p0 = x0 + y0;
        float p1 = x1 + y1;
        p0 += __shfl_xor_sync(0xFFFFFFFF, p0, 1);
        p0 += __shfl_xor_sync(0xFFFFFFFF, p0, 2);
        p1 += __shfl_xor_sync(0xFFFFFFFF, p1, 1);
        p1 += __shfl_xor_sync(0xFFFFFFFF, p1, 2);
        if (jj >= 33) p0 = -1e30f;                      // q0 inactive
        bool act1 = (jj >= d) && (jj < 33 + d);
        if (!act1) p1 = -1e30f;
        mx0 = fmaxf(mx0, p0);
        mx1 = fmaxf(mx1, p1);
        if ((jj & 3) == quarter) {
            s0own[jj >> 2] = p0;
            s1own[jj >> 2] = p1;
        }
    }

    // Dedup exp over owned slots (inactive scores -1e30 -> exp 0)
    float pj0[9], pj1[9];
    float sum0 = 0.0f, sum1 = 0.0f;
#pragma unroll
    for (int slot = 0; slot < 9; slot++) {
        int jj = slot * 4 + quarter;
        float e0 = 0.0f, e1 = 0.0f;
        if (jj < 34) {
            e0 = __expf(s0own[slot] - mx0);
            e1 = __expf(s1own[slot] - mx1);
        }
        pj0[slot] = e0; sum0 += e0;
        pj1[slot] = e1; sum1 += e1;
    }
    sum0 += __shfl_xor_sync(0xFFFFFFFF, sum0, 1);
    sum0 += __shfl_xor_sync(0xFFFFFFFF, sum0, 2);
    sum1 += __shfl_xor_sync(0xFFFFFFFF, sum1, 1);
    sum1 += __shfl_xor_sync(0xFFFFFFFF, sum1, 2);
    const float inv0 = 1.0f / sum0;
    const float inv1 = 1.0f / sum1;

    // PV loop: V row loaded once, used for both queries
    ull o0[8], o1[8];
#pragma unroll
    for (int s = 0; s < 8; s++) { o0[s] = 0ULL; o1[s] = 0ULL; }
#pragma unroll
    for (int jj = 0; jj < 34; jj++) {
        int row = base + ((jj == 33 && d == 0) ? 32 : jj);
        int src = (lane & ~3) | (jj & 3);
        float p0 = __shfl_sync(0xFFFFFFFF, pj0[jj >> 2], src);
        float p1 = __shfl_sync(0xFFFFFFFF, pj1[jj >> 2], src);
        const ull p20 = pk2(p0, p0);
        const ull p21 = pk2(p1, p1);
        const ull* vr2 = (const ull*)(Vs + row * KVP + dp);
#pragma unroll
        for (int s = 0; s < 8; s++) {
            ull vv = vr2[s];
            o0[s] = ffma2(p20, vv, o0[s]);
            o1[s] = ffma2(p21, vv, o1[s]);
        }
    }

    // Fused split epilogue for both queries
#pragma unroll
    for (int qsel = 0; qsel < 2; qsel++) {
        const ull* o = qsel ? o1 : o0;
        const float inv = qsel ? inv1 : inv0;
        const int l = qsel ? l1 : l0;
        __nv_bfloat16* orow = out2 + (size_t)(b * LSEQ + l) * K2 + h * HD + dp;
        __nv_bfloat162* ph = (__nv_bfloat162*)orow;
        __nv_bfloat162* pl = (__nv_bfloat162*)(orow + KIN);
#pragma unroll
        for (int s = 0; s < 8; s++) {
            float x, y;
            upk2(o[s], x, y);
            x *= inv; y *= inv;
            __nv_bfloat16 hx = __float2bfloat16(x);
            __nv_bfloat16 hy = __float2bfloat16(y);
            __nv_bfloat16 lx = __float2bfloat16(x - __bfloat162float(hx));
            __nv_bfloat16 ly = __float2bfloat16(y - __bfloat162float(hy));
            ph[s] = {hx, hy};
            pl[s] = {lx, ly};
        }
    }
}

// ---------------------------------------------------------------------------
// Launch
// ---------------------------------------------------------------------------
extern "C" void kernel_launch(void* const* d_in, const int* in_sizes, int n_in,
                              void* d_out, int out_size)
{
    const float* x      = (const float*)d_in[0];
    const float* w_qkv  = (const float*)d_in[1];
    const float* b_qkv  = (const float*)d_in[2];
    const float* w_proj = (const float*)d_in[3];
    const float* b_proj = (const float*)d_in[4];
    float*       out    = (float*)d_out;

    float* qkv;
    __nv_bfloat16 *a2, *wq2, *wp2;
    cudaGetSymbolAddress((void**)&qkv, g_qkv);
    cudaGetSymbolAddress((void**)&a2,  g_a2);
    cudaGetSymbolAddress((void**)&wq2, g_wq2);
    cudaGetSymbolAddress((void**)&wp2, g_wp2);

    cudaFuncSetAttribute(na1d_kernel,
                         cudaFuncAttributeMaxDynamicSharedMemorySize, ATT_SMEM);
    cudaFuncSetAttribute(gemm_wmma,
                         cudaFuncAttributeMaxDynamicSharedMemorySize, SM_TOTAL);

    // All three [hi|lo] splits in one launch
    split_bf16_all<<<5120, 256>>>((const float4*)x, a2,
                                  (const float4*)w_qkv, wq2,
                                  (const float4*)w_proj, wp2);

    // 1) QKV projection
    dim3 g1(QKVDIM / NT, MROWS / MT);
    gemm_wmma<<<g1, 512, SM_TOTAL>>>(a2, wq2, b_qkv, qkv, QKVDIM);

    // 2) Neighborhood attention (2 queries/thread, writes split operand)
    dim3 g2(LSEQ / BQ, NHEADS, BATCH);
    na1d_kernel<<<g2, 256, ATT_SMEM>>>(qkv, a2);

    // 3) Output projection
    dim3 g3(DIMSZ / NT, MROWS / MT);
    gemm_wmma<<<g3, 512, SM_TOTAL>>>(a2, wp2, b_proj, out, DIMSZ);
}